// round 3
// baseline (speedup 1.0000x reference)
#include <cuda_runtime.h>
#include <stdint.h>

#define DIM_IN 16
#define CH 128
#define DIM_OUT 99
#define MAX_NNZ 512
#define EPB 2              // edges per block
#define THREADS (EPB * 64)

// 16-byte term, read as ulonglong2: .x = ox | (oy<<32)  (byte offsets into an
// 8 KB row block), .y = {cg, cg} pre-packed for f32x2 FMA.
struct __align__(16) Term {
    unsigned int ox;
    unsigned int oy;
    float cg0;
    float cg1;
};
__device__ Term g_terms[MAX_NNZ];
__device__ int  g_rowptr[DIM_OUT + 1];

// ---------------------------------------------------------------------------
// Prep: deterministic stable counting sort of terms by mu3 into CSR layout.
// ---------------------------------------------------------------------------
__global__ void prep_kernel(const int* __restrict__ mu1,
                            const int* __restrict__ mu2,
                            const int* __restrict__ mu3,
                            const float* __restrict__ cg,
                            int nnz)
{
    __shared__ int sm3[MAX_NNZ];
    __shared__ int hist[DIM_OUT + 1];
    int t = threadIdx.x;

    if (t < DIM_OUT + 1) hist[t] = 0;
    __syncthreads();

    for (int k = t; k < nnz; k += blockDim.x) {
        int m = mu3[k];
        sm3[k] = m;
        atomicAdd(&hist[m], 1);
    }
    __syncthreads();

    if (t == 0) {
        int s = 0;
        for (int o = 0; o < DIM_OUT; o++) {
            int h = hist[o];
            g_rowptr[o] = s;
            hist[o] = s;       // becomes running row start
            s += h;
        }
        g_rowptr[DIM_OUT] = s;
    }
    __syncthreads();

    // stable scatter: rank = #earlier terms with same mu3 (deterministic)
    for (int k = t; k < nnz; k += blockDim.x) {
        int m = sm3[k];
        int rank = 0;
        for (int j = 0; j < k; j++) rank += (sm3[j] == m);
        int pos = hist[m] + rank;
        Term tm;
        tm.ox  = (unsigned int)mu1[k] * (CH * 4u);
        tm.oy  = (unsigned int)mu2[k] * (CH * 4u);
        tm.cg0 = cg[k];
        tm.cg1 = cg[k];
        g_terms[pos] = tm;
    }
}

// ---------------------------------------------------------------------------
// Main: 2 edges per 128-thread block; 64 threads per edge, one channel pair
// (float2, processed with packed f32x2 math) per thread. Terms read via
// warp-uniform __ldg (L1-resident); each output element written exactly once.
// ---------------------------------------------------------------------------
__global__ __launch_bounds__(THREADS, 6)
void tp_kernel(const float* __restrict__ x,
               const float* __restrict__ y,
               float* __restrict__ out)
{
    __shared__ __align__(16) float sx[EPB * DIM_IN * CH];   // 16 KB
    __shared__ __align__(16) float sy[EPB * DIM_IN * CH];   // 16 KB

    const int t    = threadIdx.x;        // 0..127
    const int sub  = t >> 6;             // edge within block
    const int lane = t & 63;             // channel pair within edge
    const long long ebase = (long long)blockIdx.x * EPB;

    // cooperative load of both edges' x/y tiles (contiguous in gmem)
    const float4* x4 = (const float4*)(x + ebase * (DIM_IN * CH));
    const float4* y4 = (const float4*)(y + ebase * (DIM_IN * CH));
#pragma unroll
    for (int i = 0; i < (EPB * DIM_IN * CH / 4) / THREADS; i++) {
        ((float4*)sx)[t + i * THREADS] = x4[t + i * THREADS];
        ((float4*)sy)[t + i * THREADS] = y4[t + i * THREADS];
    }
    __syncthreads();

    const char* sxb = (const char*)(sx + sub * (DIM_IN * CH)) + lane * 8;
    const char* syb = (const char*)(sy + sub * (DIM_IN * CH)) + lane * 8;
    float* oute = out + (ebase + sub) * (DIM_OUT * CH) + lane * 2;

    const ulonglong2* __restrict__ terms2 = (const ulonglong2*)g_terms;

    int k0 = 0;
#pragma unroll 1
    for (int o = 0; o < DIM_OUT; o++) {
        const int k1 = __ldg(&g_rowptr[o + 1]);
        unsigned long long acc = 0ull;   // {+0.0f, +0.0f}
#pragma unroll 4
        for (int k = k0; k < k1; ++k) {
            ulonglong2 tm = __ldg(&terms2[k]);
            unsigned int ox = (unsigned int)tm.x;
            unsigned int oy = (unsigned int)(tm.x >> 32);
            unsigned long long xv = *(const unsigned long long*)(sxb + ox);
            unsigned long long yv = *(const unsigned long long*)(syb + oy);
            unsigned long long p;
            asm("mul.rn.f32x2 %0, %1, %2;" : "=l"(p) : "l"(xv), "l"(yv));
            asm("fma.rn.f32x2 %0, %1, %2, %3;"
                : "=l"(acc) : "l"(p), "l"(tm.y), "l"(acc));
        }
        *(unsigned long long*)(oute) = acc;
        oute += CH;
        k0 = k1;
    }
}

// ---------------------------------------------------------------------------
// Inputs (metadata order): x f32 [N,16,128], y f32 [N,16,128],
//                          mu1 i32 [nnz], mu2 i32 [nnz], mu3 i32 [nnz], cg f32 [nnz]
// Output: f32 [N,99,128]
// ---------------------------------------------------------------------------
extern "C" void kernel_launch(void* const* d_in, const int* in_sizes, int n_in,
                              void* d_out, int out_size)
{
    const float* x   = (const float*)d_in[0];
    const float* y   = (const float*)d_in[1];
    const int*   mu1 = (const int*)d_in[2];
    const int*   mu2 = (const int*)d_in[3];
    const int*   mu3 = (const int*)d_in[4];
    const float* cg  = (const float*)d_in[5];

    int nnz = in_sizes[2];
    if (nnz > MAX_NNZ) nnz = MAX_NNZ;   // capacity guard (actual nnz ~350)
    int N = in_sizes[0] / (DIM_IN * CH);
    int nBlocks = (N + EPB - 1) / EPB;

    prep_kernel<<<1, 1024>>>(mu1, mu2, mu3, cg, nnz);
    tp_kernel<<<nBlocks, THREADS>>>(x, y, (float*)d_out);
}

// round 4
// speedup vs baseline: 1.6747x; 1.6747x over previous
#include <cuda_runtime.h>
#include <stdint.h>

#define DIM_IN 16
#define CH 128
#define DIM_OUT 99
#define MAX_NNZ 512
#define EPB 2              // edges per block
#define THREADS (EPB * 64)

// 16-byte term, read in-kernel as ulonglong2 (one LDS.128 broadcast):
//   .x = ox | (oy << 32)   byte offsets into the 8 KB row block
//   .y = {cg, cg}          pre-packed for f32x2 FMA
struct __align__(16) Term {
    unsigned int ox;
    unsigned int oy;
    float cg0;
    float cg1;
};
__device__ Term g_terms[MAX_NNZ];
__device__ int  g_rowptr[DIM_OUT + 1];

// ---------------------------------------------------------------------------
// Prep: deterministic stable counting sort of terms by mu3 into CSR layout.
// ---------------------------------------------------------------------------
__global__ void prep_kernel(const int* __restrict__ mu1,
                            const int* __restrict__ mu2,
                            const int* __restrict__ mu3,
                            const float* __restrict__ cg,
                            int nnz)
{
    __shared__ int sm3[MAX_NNZ];
    __shared__ int hist[DIM_OUT + 1];
    int t = threadIdx.x;

    if (t < DIM_OUT + 1) hist[t] = 0;
    __syncthreads();

    for (int k = t; k < nnz; k += blockDim.x) {
        int m = mu3[k];
        sm3[k] = m;
        atomicAdd(&hist[m], 1);
    }
    __syncthreads();

    if (t == 0) {
        int s = 0;
        for (int o = 0; o < DIM_OUT; o++) {
            int h = hist[o];
            g_rowptr[o] = s;
            hist[o] = s;       // becomes running row start
            s += h;
        }
        g_rowptr[DIM_OUT] = s;
    }
    __syncthreads();

    // stable scatter: rank = #earlier terms with same mu3 (deterministic)
    for (int k = t; k < nnz; k += blockDim.x) {
        int m = sm3[k];
        int rank = 0;
        for (int j = 0; j < k; j++) rank += (sm3[j] == m);
        int pos = hist[m] + rank;
        Term tm;
        tm.ox  = (unsigned int)mu1[k] * (CH * 4u);
        tm.oy  = (unsigned int)mu2[k] * (CH * 4u);
        tm.cg0 = cg[k];
        tm.cg1 = cg[k];
        g_terms[pos] = tm;
    }
}

// ---------------------------------------------------------------------------
// Main: 2 edges per 128-thread block; 64 threads per edge, one channel pair
// per thread processed with packed f32x2 math. Terms live in shared (LDS.128
// broadcast). Each output element is written exactly once.
// ---------------------------------------------------------------------------
__global__ __launch_bounds__(THREADS, 5)
void tp_kernel(const float* __restrict__ x,
               const float* __restrict__ y,
               float* __restrict__ out)
{
    __shared__ __align__(16) float sx[EPB * DIM_IN * CH];     // 16 KB
    __shared__ __align__(16) float sy[EPB * DIM_IN * CH];     // 16 KB
    __shared__ __align__(16) ulonglong2 sterms[MAX_NNZ];      //  8 KB
    __shared__ int srp[DIM_OUT + 1];

    const int t    = threadIdx.x;        // 0..127
    const int sub  = t >> 6;             // edge within block
    const int lane = t & 63;             // channel pair within edge
    const long long ebase = (long long)blockIdx.x * EPB;

    // cooperative load of both edges' x/y tiles (contiguous in gmem)
    const float4* x4 = (const float4*)(x + ebase * (DIM_IN * CH));
    const float4* y4 = (const float4*)(y + ebase * (DIM_IN * CH));
#pragma unroll
    for (int i = 0; i < (EPB * DIM_IN * CH / 4) / THREADS; i++) {
        ((float4*)sx)[t + i * THREADS] = x4[t + i * THREADS];
        ((float4*)sy)[t + i * THREADS] = y4[t + i * THREADS];
    }
    const ulonglong2* gt = (const ulonglong2*)g_terms;
    for (int i = t; i < MAX_NNZ; i += THREADS)   // fixed trip: fully coalesced
        sterms[i] = gt[i];
    for (int i = t; i < DIM_OUT + 1; i += THREADS)
        srp[i] = g_rowptr[i];
    __syncthreads();

    const char* sxb = (const char*)(sx + sub * (DIM_IN * CH)) + lane * 8;
    const char* syb = (const char*)(sy + sub * (DIM_IN * CH)) + lane * 8;
    float* oute = out + (ebase + sub) * (DIM_OUT * CH) + lane * 2;

    int k0 = srp[0];
#pragma unroll 1
    for (int o = 0; o < DIM_OUT; o++) {
        const int k1 = srp[o + 1];
        unsigned long long acc = 0ull;   // {+0.0f, +0.0f}
#pragma unroll 4
        for (int k = k0; k < k1; ++k) {
            ulonglong2 tm = sterms[k];
            unsigned int ox = (unsigned int)tm.x;
            unsigned int oy = (unsigned int)(tm.x >> 32);
            unsigned long long xv = *(const unsigned long long*)(sxb + ox);
            unsigned long long yv = *(const unsigned long long*)(syb + oy);
            unsigned long long p;
            asm("mul.rn.f32x2 %0, %1, %2;" : "=l"(p) : "l"(xv), "l"(yv));
            asm("fma.rn.f32x2 %0, %1, %2, %3;"
                : "=l"(acc) : "l"(p), "l"(tm.y), "l"(acc));
        }
        *(unsigned long long*)(oute) = acc;
        oute += CH;
        k0 = k1;
    }
}

// ---------------------------------------------------------------------------
// Inputs (metadata order): x f32 [N,16,128], y f32 [N,16,128],
//                          mu1 i32 [nnz], mu2 i32 [nnz], mu3 i32 [nnz], cg f32 [nnz]
// Output: f32 [N,99,128]
// ---------------------------------------------------------------------------
extern "C" void kernel_launch(void* const* d_in, const int* in_sizes, int n_in,
                              void* d_out, int out_size)
{
    const float* x   = (const float*)d_in[0];
    const float* y   = (const float*)d_in[1];
    const int*   mu1 = (const int*)d_in[2];
    const int*   mu2 = (const int*)d_in[3];
    const int*   mu3 = (const int*)d_in[4];
    const float* cg  = (const float*)d_in[5];

    int nnz = in_sizes[2];
    if (nnz > MAX_NNZ) nnz = MAX_NNZ;   // capacity guard (actual nnz ~350)
    int N = in_sizes[0] / (DIM_IN * CH);
    int nBlocks = (N + EPB - 1) / EPB;

    prep_kernel<<<1, 1024>>>(mu1, mu2, mu3, cg, nnz);
    tp_kernel<<<nBlocks, THREADS>>>(x, y, (float*)d_out);
}

// round 5
// speedup vs baseline: 1.8767x; 1.1206x over previous
#include <cuda_runtime.h>
#include <stdint.h>

#define DIM_IN 16
#define CH 128
#define DIM_OUT 99
#define MAX_NNZ 512
#define EPB 2              // edges per block
#define THREADS (EPB * 64)

// 8-byte term, read with one LDS.64 broadcast:
//   .x = ox | (oy << 16)   u16 byte offsets into the 8 KB row block (max 7680)
//   .y = cg bits
__device__ uint2 g_terms[MAX_NNZ];
__device__ int   g_rowptr[DIM_OUT + 1];

// ---------------------------------------------------------------------------
// Prep: deterministic stable counting sort of terms by mu3 into CSR layout.
// ---------------------------------------------------------------------------
__global__ void prep_kernel(const int* __restrict__ mu1,
                            const int* __restrict__ mu2,
                            const int* __restrict__ mu3,
                            const float* __restrict__ cg,
                            int nnz)
{
    __shared__ int sm3[MAX_NNZ];
    __shared__ int hist[DIM_OUT + 1];
    int t = threadIdx.x;

    if (t < DIM_OUT + 1) hist[t] = 0;
    __syncthreads();

    for (int k = t; k < nnz; k += blockDim.x) {
        int m = mu3[k];
        sm3[k] = m;
        atomicAdd(&hist[m], 1);
    }
    __syncthreads();

    if (t == 0) {
        int s = 0;
        for (int o = 0; o < DIM_OUT; o++) {
            int h = hist[o];
            g_rowptr[o] = s;
            hist[o] = s;       // becomes running row start
            s += h;
        }
        g_rowptr[DIM_OUT] = s;
    }
    __syncthreads();

    // stable scatter: rank = #earlier terms with same mu3 (deterministic)
    for (int k = t; k < nnz; k += blockDim.x) {
        int m = sm3[k];
        int rank = 0;
        for (int j = 0; j < k; j++) rank += (sm3[j] == m);
        int pos = hist[m] + rank;
        unsigned int ox = (unsigned int)mu1[k] * (CH * 4u);   // <= 7680, fits u16
        unsigned int oy = (unsigned int)mu2[k] * (CH * 4u);
        uint2 tm;
        tm.x = ox | (oy << 16);
        tm.y = __float_as_uint(cg[k]);
        g_terms[pos] = tm;
    }
}

// ---------------------------------------------------------------------------
// Main: 2 edges per 128-thread block; 64 threads per edge, one channel pair
// per thread, packed f32x2 math. 8-byte terms in shared (LDS.64 broadcast,
// 1 wavefront). Each output element is written exactly once.
// ---------------------------------------------------------------------------
__global__ __launch_bounds__(THREADS, 6)
void tp_kernel(const float* __restrict__ x,
               const float* __restrict__ y,
               float* __restrict__ out)
{
    __shared__ __align__(16) float sx[EPB * DIM_IN * CH];   // 16 KB
    __shared__ __align__(16) float sy[EPB * DIM_IN * CH];   // 16 KB
    __shared__ __align__(16) uint2 sterms[MAX_NNZ];         //  4 KB
    __shared__ int srp[DIM_OUT + 1];

    const int t    = threadIdx.x;        // 0..127
    const int sub  = t >> 6;             // edge within block
    const int lane = t & 63;             // channel pair within edge
    const long long ebase = (long long)blockIdx.x * EPB;

    // cooperative load of both edges' x/y tiles (contiguous in gmem)
    const float4* x4 = (const float4*)(x + ebase * (DIM_IN * CH));
    const float4* y4 = (const float4*)(y + ebase * (DIM_IN * CH));
#pragma unroll
    for (int i = 0; i < (EPB * DIM_IN * CH / 4) / THREADS; i++) {
        ((float4*)sx)[t + i * THREADS] = x4[t + i * THREADS];
        ((float4*)sy)[t + i * THREADS] = y4[t + i * THREADS];
    }
#pragma unroll
    for (int i = 0; i < MAX_NNZ / THREADS; i++)
        sterms[t + i * THREADS] = g_terms[t + i * THREADS];
    if (t < DIM_OUT + 1)
        srp[t] = g_rowptr[t];
    __syncthreads();

    const char* sxb = (const char*)(sx + sub * (DIM_IN * CH)) + lane * 8;
    const char* syb = (const char*)(sy + sub * (DIM_IN * CH)) + lane * 8;
    float* oute = out + (ebase + sub) * (DIM_OUT * CH) + lane * 2;

    int k0 = srp[0];
#pragma unroll 1
    for (int o = 0; o < DIM_OUT; o++) {
        const int k1 = srp[o + 1];
        unsigned long long acc = 0ull;   // {+0.0f, +0.0f}
#pragma unroll 4
        for (int k = k0; k < k1; ++k) {
            uint2 tm = sterms[k];
            unsigned int ox = tm.x & 0xFFFFu;
            unsigned int oy = tm.x >> 16;
            unsigned long long cgp;
            asm("mov.b64 %0, {%1, %1};" : "=l"(cgp) : "r"(tm.y));
            unsigned long long xv = *(const unsigned long long*)(sxb + ox);
            unsigned long long yv = *(const unsigned long long*)(syb + oy);
            unsigned long long p;
            asm("mul.rn.f32x2 %0, %1, %2;" : "=l"(p) : "l"(xv), "l"(yv));
            asm("fma.rn.f32x2 %0, %1, %2, %3;"
                : "=l"(acc) : "l"(p), "l"(cgp), "l"(acc));
        }
        *(unsigned long long*)(oute) = acc;
        oute += CH;
        k0 = k1;
    }
}

// ---------------------------------------------------------------------------
// Inputs (metadata order): x f32 [N,16,128], y f32 [N,16,128],
//                          mu1 i32 [nnz], mu2 i32 [nnz], mu3 i32 [nnz], cg f32 [nnz]
// Output: f32 [N,99,128]
// ---------------------------------------------------------------------------
extern "C" void kernel_launch(void* const* d_in, const int* in_sizes, int n_in,
                              void* d_out, int out_size)
{
    const float* x   = (const float*)d_in[0];
    const float* y   = (const float*)d_in[1];
    const int*   mu1 = (const int*)d_in[2];
    const int*   mu2 = (const int*)d_in[3];
    const int*   mu3 = (const int*)d_in[4];
    const float* cg  = (const float*)d_in[5];

    int nnz = in_sizes[2];
    if (nnz > MAX_NNZ) nnz = MAX_NNZ;   // capacity guard (actual nnz ~350)
    int N = in_sizes[0] / (DIM_IN * CH);
    int nBlocks = (N + EPB - 1) / EPB;

    prep_kernel<<<1, 1024>>>(mu1, mu2, mu3, cg, nnz);
    tp_kernel<<<nBlocks, THREADS>>>(x, y, (float*)d_out);
}